// round 3
// baseline (speedup 1.0000x reference)
#include <cuda_runtime.h>

#define NUM_LAYERS 24
#define LN_EPS 1e-5f
#define THREADS 256

typedef unsigned long long ull;

// ---- packed f32x2 helpers (Blackwell FFMA2 path, PTX-only) ----
__device__ __forceinline__ ull pack2(float lo, float hi) {
    ull r; asm("mov.b64 %0, {%1, %2};" : "=l"(r) : "f"(lo), "f"(hi)); return r;
}
__device__ __forceinline__ void unpack2(ull v, float& lo, float& hi) {
    asm("mov.b64 {%0, %1}, %2;" : "=f"(lo), "=f"(hi) : "l"(v));
}
__device__ __forceinline__ void ffma2(ull& acc, ull a, ull b) {
    asm("fma.rn.f32x2 %0, %1, %2, %0;" : "+l"(acc) : "l"(a), "l"(b));
}

__global__ __launch_bounds__(THREADS) void router_kernel(
    const float* __restrict__ x,
    const float* __restrict__ ln_w,
    const float* __restrict__ ln_b,
    const float* __restrict__ W1,
    const float* __restrict__ b1,
    const float* __restrict__ W2,
    const float* __restrict__ b2,
    const float* __restrict__ W3,
    const float* __restrict__ b3,
    float* __restrict__ out,
    int n_rows)
{
    // ---- shared staging ----
    __shared__ __align__(16) float sW2[32 * 64];   // row-major [j][k]; LDS.128 => 2 packed k-pairs
    __shared__ __align__(8)  float sW1p[5 * 64];   // [k][jp pairs]: {W1[2jp][k], W1[2jp+1][k]}
    __shared__ __align__(8)  float sB1[64];        // natural pairs {b1[2jp], b1[2jp+1]}
    __shared__ float sB2[32];
    __shared__ __align__(8)  float sW3p[32];       // natural pairs
    __shared__ float sB3;
    __shared__ float sLnW[NUM_LAYERS * 4];
    __shared__ float sLnB[NUM_LAYERS * 4];
    __shared__ float sx[THREADS * 5];

    const int tid = threadIdx.x;

    // cooperative weight staging (once per block)
    for (int i = tid; i < 32 * 64; i += THREADS) sW2[i] = W2[i];
    if (tid < 32) {
        // build W1 output-pair pack: sW1p[k*64 + 2*jp + {0,1}] = W1[2jp..2jp+1][k]
        #pragma unroll
        for (int k = 0; k < 5; k++) {
            sW1p[k * 64 + 2 * tid + 0] = W1[(2 * tid + 0) * 5 + k];
            sW1p[k * 64 + 2 * tid + 1] = W1[(2 * tid + 1) * 5 + k];
        }
        sB2[tid]  = b2[tid];
        sW3p[tid] = W3[tid];
    }
    if (tid < 64) sB1[tid] = b1[tid];
    if (tid == 0) sB3 = b3[0];
    for (int i = tid; i < NUM_LAYERS * 4; i += THREADS) {
        sLnW[i] = ln_w[i];
        sLnB[i] = ln_b[i];
    }

    // coalesced input slab: 256 rows * 5 floats contiguous
    const long long base_row = (long long)blockIdx.x * THREADS;
    const float* xin = x + base_row * 5;
    #pragma unroll
    for (int i = tid; i < THREADS * 5; i += THREADS) sx[i] = xin[i];

    __syncthreads();

    const long long row = base_row + tid;
    if (row >= n_rows) return;

    // ---- per-row features (stride 5: gcd(5,32)=1, conflict-free) ----
    const float f0  = sx[tid * 5 + 0];
    const float f1  = sx[tid * 5 + 1];
    const float f2  = sx[tid * 5 + 2];
    const float f3  = sx[tid * 5 + 3];
    const float pos = sx[tid * 5 + 4];

    // layernorm over 4 feats
    const float mean = (f0 + f1 + f2 + f3) * 0.25f;
    const float d0 = f0 - mean, d1 = f1 - mean, d2 = f2 - mean, d3 = f3 - mean;
    const float var  = (d0 * d0 + d1 * d1 + d2 * d2 + d3 * d3) * 0.25f;
    const float rstd = rsqrtf(var + LN_EPS);

    int lid = (int)(pos * (float)NUM_LAYERS);
    lid = max(0, min(NUM_LAYERS - 1, lid));

    const float n0 = d0 * rstd * sLnW[lid * 4 + 0] + sLnB[lid * 4 + 0];
    const float n1 = d1 * rstd * sLnW[lid * 4 + 1] + sLnB[lid * 4 + 1];
    const float n2 = d2 * rstd * sLnW[lid * 4 + 2] + sLnB[lid * 4 + 2];
    const float n3 = d3 * rstd * sLnW[lid * 4 + 3] + sLnB[lid * 4 + 3];

    // broadcast-packed inputs for layer 1
    ull nb[5];
    nb[0] = pack2(n0, n0);
    nb[1] = pack2(n1, n1);
    nb[2] = pack2(n2, n2);
    nb[3] = pack2(n3, n3);
    nb[4] = pack2(pos, pos);

    // ---- layer 1: 5 -> 64, output-pair packed (acc = {h1[2jp], h1[2jp+1]}) ----
    // h1p[i] ends up holding the {h1[2i], h1[2i+1]} pair layer 2 consumes.
    ull h1p[32];
    #pragma unroll
    for (int jp = 0; jp < 32; jp++) {
        const float2 bias = *reinterpret_cast<const float2*>(&sB1[2 * jp]);
        ull acc = pack2(bias.x, bias.y);
        #pragma unroll
        for (int k = 0; k < 5; k++) {
            const float2 w = *reinterpret_cast<const float2*>(&sW1p[k * 64 + 2 * jp]);
            ffma2(acc, pack2(w.x, w.y), nb[k]);
        }
        float lo, hi;
        unpack2(acc, lo, hi);
        h1p[jp] = pack2(fmaxf(lo, 0.0f), fmaxf(hi, 0.0f));
    }

    // ---- layer 2: 64 -> 32, even/odd-k packed accumulation ----
    // One LDS.128 delivers two packed weight k-pairs; broadcast across warp.
    float h2[32];
    #pragma unroll
    for (int j = 0; j < 32; j++) {
        const ulonglong2* w2v = reinterpret_cast<const ulonglong2*>(&sW2[j * 64]);
        ull acc = pack2(sB2[j], 0.0f);
        #pragma unroll
        for (int k8 = 0; k8 < 16; k8++) {
            const ulonglong2 w = w2v[k8];
            ffma2(acc, w.x, h1p[2 * k8 + 0]);
            ffma2(acc, w.y, h1p[2 * k8 + 1]);
        }
        float lo, hi;
        unpack2(acc, lo, hi);
        h2[j] = fmaxf(lo + hi, 0.0f);
    }

    // ---- layer 3: 32 -> 1, packed pairs ----
    ull acc3 = pack2(sB3, 0.0f);
    #pragma unroll
    for (int jp = 0; jp < 16; jp++) {
        const float2 w = *reinterpret_cast<const float2*>(&sW3p[2 * jp]);
        ffma2(acc3, pack2(w.x, w.y), pack2(h2[2 * jp], h2[2 * jp + 1]));
    }
    float lo, hi;
    unpack2(acc3, lo, hi);
    out[row] = lo + hi;
}

extern "C" void kernel_launch(void* const* d_in, const int* in_sizes, int n_in,
                              void* d_out, int out_size)
{
    const float* x    = (const float*)d_in[0];
    const float* ln_w = (const float*)d_in[1];
    const float* ln_b = (const float*)d_in[2];
    const float* W1   = (const float*)d_in[3];
    const float* b1   = (const float*)d_in[4];
    const float* W2   = (const float*)d_in[5];
    const float* b2   = (const float*)d_in[6];
    const float* W3   = (const float*)d_in[7];
    const float* b3   = (const float*)d_in[8];
    float* out = (float*)d_out;

    const int n_rows = out_size;
    const int blocks = (n_rows + THREADS - 1) / THREADS;

    router_kernel<<<blocks, THREADS>>>(x, ln_w, ln_b, W1, b1, W2, b2, W3, b3,
                                       out, n_rows);
}

// round 7
// speedup vs baseline: 3.2365x; 3.2365x over previous
#include <cuda_runtime.h>
#include <cstdint>

#define NUM_LAYERS 24
#define LN_EPS 1e-5f
#define TPB 128
#define WARPS 4
#define CHUNKS_PER_WARP 8
#define ROWS_PER_CTA (WARPS * CHUNKS_PER_WARP * 32)   // 1024
#define QS 36   // q-row stride in words for transposed A planes (conflict-free)

// pack {lo -> low 16, hi -> high 16} as bf16x2
static __device__ __forceinline__ uint32_t bf16x2_of(float lo, float hi) {
    uint32_t r;
    asm("cvt.rn.bf16x2.f32 %0, %1, %2;" : "=r"(r) : "f"(hi), "f"(lo));
    return r;
}

// split (a,b) into bf16 pair hi2 and residual pair lo2 (a in low half)
static __device__ __forceinline__ void split_pair(float a, float b,
                                                  uint32_t& hi2, uint32_t& lo2) {
    hi2 = bf16x2_of(a, b);
    float ra = __uint_as_float(hi2 << 16);
    float rb = __uint_as_float(hi2 & 0xFFFF0000u);
    lo2 = bf16x2_of(a - ra, b - rb);
}

// D += A @ B  (m16n8k16, bf16 in, f32 accum) — baseline PTX, works at compute_103
static __device__ __forceinline__ void mma_bf16(
    float& c0, float& c1, float& c2, float& c3,
    uint32_t a0, uint32_t a1, uint32_t a2, uint32_t a3,
    uint32_t b0, uint32_t b1)
{
    asm volatile(
        "mma.sync.aligned.m16n8k16.row.col.f32.bf16.bf16.f32 "
        "{%0,%1,%2,%3}, {%4,%5,%6,%7}, {%8,%9}, {%0,%1,%2,%3};"
        : "+f"(c0), "+f"(c1), "+f"(c2), "+f"(c3)
        : "r"(a0), "r"(a1), "r"(a2), "r"(a3), "r"(b0), "r"(b1));
}

struct Smem {
    uint32_t A[WARPS][2][32 * QS];   // [warp][0=hi,1=lo] transposed h1 pairs: word = q*QS + r
    float    W1t[5 * 64];            // [k][j]
    float    B1v[64];
    float    LnW[NUM_LAYERS * 4];
    float    LnB[NUM_LAYERS * 4];
};

__global__ __launch_bounds__(TPB) void router_kernel(
    const float* __restrict__ x,
    const float* __restrict__ ln_w,
    const float* __restrict__ ln_b,
    const float* __restrict__ W1,
    const float* __restrict__ b1,
    const float* __restrict__ W2,
    const float* __restrict__ b2,
    const float* __restrict__ W3,
    const float* __restrict__ b3,
    float* __restrict__ out,
    int n_rows)
{
    __shared__ Smem sm;
    const int tid  = threadIdx.x;
    const int warp = tid >> 5;
    const int lane = tid & 31;
    const int g = lane >> 2;     // 0..7
    const int t = lane & 3;      // 0..3

    // ---- stage small weights to smem (once) ----
    if (tid < 64) {
        #pragma unroll
        for (int k = 0; k < 5; k++) sm.W1t[k * 64 + tid] = W1[tid * 5 + k];
        sm.B1v[tid] = b1[tid];
    }
    if (tid < NUM_LAYERS * 4) { sm.LnW[tid] = ln_w[tid]; sm.LnB[tid] = ln_b[tid]; }
    __syncthreads();

    // ---- W2 fragments (per-lane registers, loaded once) ----
    // B fragment (col-major B = W2 row-major): b0 = {W2[8nt+g][16kt+2t], +1},
    // b1 = same at k+8. Split into hi/lo bf16 pairs.
    uint32_t bh0[4][4], bh1[4][4], bl0[4][4], bl1[4][4];
    #pragma unroll
    for (int nt = 0; nt < 4; nt++) {
        #pragma unroll
        for (int kt = 0; kt < 4; kt++) {
            const float* wrow = W2 + (8 * nt + g) * 64 + 16 * kt + 2 * t;
            const float2 w0 = *reinterpret_cast<const float2*>(wrow);
            const float2 w1 = *reinterpret_cast<const float2*>(wrow + 8);
            split_pair(w0.x, w0.y, bh0[nt][kt], bl0[nt][kt]);
            split_pair(w1.x, w1.y, bh1[nt][kt], bl1[nt][kt]);
        }
    }

    // per-lane b2/W3 for this lane's output columns (cols 8nt+2t, +1)
    float2 b2v[4], w3v[4];
    #pragma unroll
    for (int nt = 0; nt < 4; nt++) {
        const int col = 8 * nt + 2 * t;
        b2v[nt] = *reinterpret_cast<const float2*>(b2 + col);
        w3v[nt] = *reinterpret_cast<const float2*>(W3 + col);
    }
    const float b3v = b3[0];

    uint32_t* __restrict__ Phi = sm.A[warp][0];
    uint32_t* __restrict__ Plo = sm.A[warp][1];

    const long long warp_row0 = (long long)blockIdx.x * ROWS_PER_CTA
                              + (long long)warp * (CHUNKS_PER_WARP * 32);

    for (int ch = 0; ch < CHUNKS_PER_WARP; ch++) {
        const long long row0 = warp_row0 + ch * 32;

        // ---- scalar LN + layer1 for row = row0 + lane ----
        const float* xr = x + (row0 + lane) * 5;
        const float f0 = xr[0], f1 = xr[1], f2 = xr[2], f3 = xr[3], pos = xr[4];

        const float mean = (f0 + f1 + f2 + f3) * 0.25f;
        const float d0 = f0 - mean, d1 = f1 - mean, d2 = f2 - mean, d3 = f3 - mean;
        const float var  = (d0 * d0 + d1 * d1 + d2 * d2 + d3 * d3) * 0.25f;
        const float rstd = rsqrtf(var + LN_EPS);

        int lid = (int)(pos * (float)NUM_LAYERS);
        lid = max(0, min(NUM_LAYERS - 1, lid));

        float nk[5];
        nk[0] = d0 * rstd * sm.LnW[lid * 4 + 0] + sm.LnB[lid * 4 + 0];
        nk[1] = d1 * rstd * sm.LnW[lid * 4 + 1] + sm.LnB[lid * 4 + 1];
        nk[2] = d2 * rstd * sm.LnW[lid * 4 + 2] + sm.LnB[lid * 4 + 2];
        nk[3] = d3 * rstd * sm.LnW[lid * 4 + 3] + sm.LnB[lid * 4 + 3];
        nk[4] = pos;

        // layer1 in groups of 8 outputs; split to bf16 hi/lo pairs; store transposed
        #pragma unroll
        for (int c = 0; c < 8; c++) {
            float hv[8];
            {
                const float4 ba = *reinterpret_cast<const float4*>(&sm.B1v[c * 8]);
                const float4 bb = *reinterpret_cast<const float4*>(&sm.B1v[c * 8 + 4]);
                hv[0] = ba.x; hv[1] = ba.y; hv[2] = ba.z; hv[3] = ba.w;
                hv[4] = bb.x; hv[5] = bb.y; hv[6] = bb.z; hv[7] = bb.w;
            }
            #pragma unroll
            for (int k = 0; k < 5; k++) {
                const float4 wa = *reinterpret_cast<const float4*>(&sm.W1t[k * 64 + c * 8]);
                const float4 wb = *reinterpret_cast<const float4*>(&sm.W1t[k * 64 + c * 8 + 4]);
                hv[0] = fmaf(wa.x, nk[k], hv[0]);
                hv[1] = fmaf(wa.y, nk[k], hv[1]);
                hv[2] = fmaf(wa.z, nk[k], hv[2]);
                hv[3] = fmaf(wa.w, nk[k], hv[3]);
                hv[4] = fmaf(wb.x, nk[k], hv[4]);
                hv[5] = fmaf(wb.y, nk[k], hv[5]);
                hv[6] = fmaf(wb.z, nk[k], hv[6]);
                hv[7] = fmaf(wb.w, nk[k], hv[7]);
            }
            #pragma unroll
            for (int i = 0; i < 8; i++) hv[i] = fmaxf(hv[i], 0.0f);

            #pragma unroll
            for (int p = 0; p < 4; p++) {
                uint32_t hi, lo;
                split_pair(hv[2 * p], hv[2 * p + 1], hi, lo);
                const int q = c * 4 + p;                 // k-pair index 0..31
                Phi[q * QS + lane] = hi;                 // bank = 4q+lane : conflict-free
                Plo[q * QS + lane] = lo;
            }
        }
        __syncwarp();

        // ---- layer 2 via mma.sync: rows 16*mt+g(+8), cols 8*nt+2t(+1) ----
        #pragma unroll
        for (int mt = 0; mt < 2; mt++) {
            float C[4][4];
            #pragma unroll
            for (int nt = 0; nt < 4; nt++) {
                C[nt][0] = 0.f; C[nt][1] = 0.f; C[nt][2] = 0.f; C[nt][3] = 0.f;
            }

            const int r0 = 16 * mt + g;
            const int r1 = r0 + 8;
            #pragma unroll
            for (int kt = 0; kt < 4; kt++) {
                const int q0 = 8 * kt + t;      // k = 16kt + 2t
                const int q1 = q0 + 4;          // k = 16kt + 8 + 2t
                const uint32_t a0h = Phi[q0 * QS + r0];
                const uint32_t a1h = Phi[q0 * QS + r1];
                const uint32_t a2h = Phi[q1 * QS + r0];
                const uint32_t a3h = Phi[q1 * QS + r1];
                const uint32_t a0l = Plo[q0 * QS + r0];
                const uint32_t a1l = Plo[q0 * QS + r1];
                const uint32_t a2l = Plo[q1 * QS + r0];
                const uint32_t a3l = Plo[q1 * QS + r1];
                #pragma unroll
                for (int nt = 0; nt < 4; nt++) {
                    mma_bf16(C[nt][0], C[nt][1], C[nt][2], C[nt][3],
                             a0h, a1h, a2h, a3h, bh0[nt][kt], bh1[nt][kt]);
                    mma_bf16(C[nt][0], C[nt][1], C[nt][2], C[nt][3],
                             a0h, a1h, a2h, a3h, bl0[nt][kt], bl1[nt][kt]);
                    mma_bf16(C[nt][0], C[nt][1], C[nt][2], C[nt][3],
                             a0l, a1l, a2l, a3l, bh0[nt][kt], bh1[nt][kt]);
                }
            }

            // ---- epilogue: +b2, relu, dot W3 over this lane's 8 cols; quad-reduce ----
            float pA = 0.f, pB = 0.f;
            #pragma unroll
            for (int nt = 0; nt < 4; nt++) {
                const float v0 = fmaxf(C[nt][0] + b2v[nt].x, 0.0f);
                const float v1 = fmaxf(C[nt][1] + b2v[nt].y, 0.0f);
                const float v2 = fmaxf(C[nt][2] + b2v[nt].x, 0.0f);
                const float v3 = fmaxf(C[nt][3] + b2v[nt].y, 0.0f);
                pA = fmaf(v0, w3v[nt].x, fmaf(v1, w3v[nt].y, pA));
                pB = fmaf(v2, w3v[nt].x, fmaf(v3, w3v[nt].y, pB));
            }
            pA += __shfl_xor_sync(0xFFFFFFFFu, pA, 1);
            pA += __shfl_xor_sync(0xFFFFFFFFu, pA, 2);
            pB += __shfl_xor_sync(0xFFFFFFFFu, pB, 1);
            pB += __shfl_xor_sync(0xFFFFFFFFu, pB, 2);
            if (t == 0) {
                out[row0 + r0] = pA + b3v;
                out[row0 + r1] = pB + b3v;
            }
        }
        __syncwarp();   // A planes reusable next chunk
    }
}

extern "C" void kernel_launch(void* const* d_in, const int* in_sizes, int n_in,
                              void* d_out, int out_size)
{
    const float* x    = (const float*)d_in[0];
    const float* ln_w = (const float*)d_in[1];
    const float* ln_b = (const float*)d_in[2];
    const float* W1   = (const float*)d_in[3];
    const float* b1   = (const float*)d_in[4];
    const float* W2   = (const float*)d_in[5];
    const float* b2   = (const float*)d_in[6];
    const float* W3   = (const float*)d_in[7];
    const float* b3   = (const float*)d_in[8];
    float* out = (float*)d_out;

    const int n_rows = out_size;                    // 2,097,152
    const int blocks = n_rows / ROWS_PER_CTA;       // 2048, exact

    router_kernel<<<blocks, TPB>>>(x, ln_w, ln_b, W1, b1, W2, b2, W3, b3,
                                   out, n_rows);
}

// round 8
// speedup vs baseline: 3.4696x; 1.0720x over previous
#include <cuda_runtime.h>
#include <cstdint>

#define NUM_LAYERS 24
#define LN_EPS 1e-5f
#define TPB 128
#define WARPS 4
#define CHUNKS_PER_WARP 8
#define ROWS_PER_CTA (WARPS * CHUNKS_PER_WARP * 32)   // 1024

// pack {lo -> low 16, hi -> high 16} as bf16x2
static __device__ __forceinline__ uint32_t bf16x2_of(float lo, float hi) {
    uint32_t r;
    asm("cvt.rn.bf16x2.f32 %0, %1, %2;" : "=r"(r) : "f"(hi), "f"(lo));
    return r;
}

// split (a,b) into bf16 pair hi2 and residual pair lo2 (a in low half)
static __device__ __forceinline__ void split_pair(float a, float b,
                                                  uint32_t& hi2, uint32_t& lo2) {
    hi2 = bf16x2_of(a, b);
    float ra = __uint_as_float(hi2 << 16);
    float rb = __uint_as_float(hi2 & 0xFFFF0000u);
    lo2 = bf16x2_of(a - ra, b - rb);
}

// D += A @ B  (m16n8k16, bf16, f32 accum)
static __device__ __forceinline__ void mma_k16(
    float* c, uint32_t a0, uint32_t a1, uint32_t a2, uint32_t a3,
    uint32_t b0, uint32_t b1)
{
    asm volatile(
        "mma.sync.aligned.m16n8k16.row.col.f32.bf16.bf16.f32 "
        "{%0,%1,%2,%3}, {%4,%5,%6,%7}, {%8,%9}, {%0,%1,%2,%3};"
        : "+f"(c[0]), "+f"(c[1]), "+f"(c[2]), "+f"(c[3])
        : "r"(a0), "r"(a1), "r"(a2), "r"(a3), "r"(b0), "r"(b1));
}

// D += A @ B  (m16n8k8, bf16, f32 accum)
static __device__ __forceinline__ void mma_k8(
    float* c, uint32_t a0, uint32_t a1, uint32_t b0)
{
    asm volatile(
        "mma.sync.aligned.m16n8k8.row.col.f32.bf16.bf16.f32 "
        "{%0,%1,%2,%3}, {%4,%5}, {%6}, {%0,%1,%2,%3};"
        : "+f"(c[0]), "+f"(c[1]), "+f"(c[2]), "+f"(c[3])
        : "r"(a0), "r"(a1), "r"(b0));
}

static __device__ __forceinline__ uint32_t shfl_u32(uint32_t v, int src) {
    return __shfl_sync(0xFFFFFFFFu, v, src);
}

__global__ __launch_bounds__(TPB) void router_kernel(
    const float* __restrict__ x,
    const float* __restrict__ ln_w,
    const float* __restrict__ ln_b,
    const float* __restrict__ W1,
    const float* __restrict__ b1,
    const float* __restrict__ W2,
    const float* __restrict__ b2,
    const float* __restrict__ W3,
    const float* __restrict__ b3,
    float* __restrict__ out,
    int n_rows)
{
    __shared__ float sLnW[NUM_LAYERS * 4];
    __shared__ float sLnB[NUM_LAYERS * 4];

    const int tid  = threadIdx.x;
    const int lane = tid & 31;
    const int warp = tid >> 5;
    const int g = lane >> 2;     // 0..7
    const int t = lane & 3;      // 0..3

    if (tid < NUM_LAYERS * 4) { sLnW[tid] = ln_w[tid]; sLnB[tid] = ln_b[tid]; }
    __syncthreads();

    // ---- W1 B-fragments (m16n8k8, 8 n-tiles), hi/lo split; k = 2t,2t+1 (>=5 -> 0) ----
    uint32_t w1h[8], w1l[8];
    #pragma unroll
    for (int nt = 0; nt < 8; nt++) {
        const float* wr = W1 + (8 * nt + g) * 5;
        const float w0 = (2 * t     < 5) ? wr[2 * t]     : 0.0f;
        const float w1v = (2 * t + 1 < 5) ? wr[2 * t + 1] : 0.0f;
        split_pair(w0, w1v, w1h[nt], w1l[nt]);
    }

    // ---- W2 B-fragments (m16n8k16, 4 n-tiles x 4 k-tiles), hi/lo ----
    uint32_t bh0[4][4], bh1[4][4], bl0[4][4], bl1[4][4];
    #pragma unroll
    for (int nt = 0; nt < 4; nt++) {
        #pragma unroll
        for (int kt = 0; kt < 4; kt++) {
            const float* wrow = W2 + (8 * nt + g) * 64 + 16 * kt + 2 * t;
            const float2 w0 = *reinterpret_cast<const float2*>(wrow);
            const float2 w1v = *reinterpret_cast<const float2*>(wrow + 8);
            split_pair(w0.x, w0.y, bh0[nt][kt], bl0[nt][kt]);
            split_pair(w1v.x, w1v.y, bh1[nt][kt], bl1[nt][kt]);
        }
    }

    // per-lane bias/weight pairs for this lane's columns
    float2 b1v[8];
    #pragma unroll
    for (int nt = 0; nt < 8; nt++)
        b1v[nt] = *reinterpret_cast<const float2*>(b1 + 8 * nt + 2 * t);
    float2 b2v[4], w3v[4];
    #pragma unroll
    for (int nt = 0; nt < 4; nt++) {
        b2v[nt] = *reinterpret_cast<const float2*>(b2 + 8 * nt + 2 * t);
        w3v[nt] = *reinterpret_cast<const float2*>(W3 + 8 * nt + 2 * t);
    }
    const float b3v = b3[0];

    const long long warp_row0 = (long long)blockIdx.x * ROWS_PER_CTA
                              + (long long)warp * (CHUNKS_PER_WARP * 32);

    for (int ch = 0; ch < CHUNKS_PER_WARP; ch++) {
        const long long row0 = warp_row0 + ch * 32;

        // ---- scalar LN for row = row0 + lane ----
        const float* xr = x + (row0 + lane) * 5;
        const float f0 = xr[0], f1 = xr[1], f2 = xr[2], f3 = xr[3], pos = xr[4];

        const float mean = (f0 + f1 + f2 + f3) * 0.25f;
        const float d0 = f0 - mean, d1 = f1 - mean, d2 = f2 - mean, d3 = f3 - mean;
        const float var  = (d0 * d0 + d1 * d1 + d2 * d2 + d3 * d3) * 0.25f;
        const float rstd = rsqrtf(var + LN_EPS);

        int lid = (int)(pos * (float)NUM_LAYERS);
        lid = max(0, min(NUM_LAYERS - 1, lid));

        const float n0 = d0 * rstd * sLnW[lid * 4 + 0] + sLnB[lid * 4 + 0];
        const float n1 = d1 * rstd * sLnW[lid * 4 + 1] + sLnB[lid * 4 + 1];
        const float n2 = d2 * rstd * sLnW[lid * 4 + 2] + sLnB[lid * 4 + 2];
        const float n3 = d3 * rstd * sLnW[lid * 4 + 3] + sLnB[lid * 4 + 3];

        // feature pairs (this lane's row), hi/lo split: {n0,n1},{n2,n3},{pos,0}
        uint32_t ph[3], pl[3];
        split_pair(n0, n1, ph[0], pl[0]);
        split_pair(n2, n3, ph[1], pl[1]);
        split_pair(pos, 0.0f, ph[2], pl[2]);

        #pragma unroll
        for (int mt = 0; mt < 2; mt++) {
            const int src0 = 16 * mt + g;       // row for a0
            const int src1 = src0 + 8;          // row for a1

            // transpose features via shuffle (12 shfl), then per-lane k-select
            const uint32_t s0h = shfl_u32(ph[0], src0);
            const uint32_t s1h = shfl_u32(ph[1], src0);
            const uint32_t s2h = shfl_u32(ph[2], src0);
            const uint32_t s0l = shfl_u32(pl[0], src0);
            const uint32_t s1l = shfl_u32(pl[1], src0);
            const uint32_t s2l = shfl_u32(pl[2], src0);
            const uint32_t u0h = shfl_u32(ph[0], src1);
            const uint32_t u1h = shfl_u32(ph[1], src1);
            const uint32_t u2h = shfl_u32(ph[2], src1);
            const uint32_t u0l = shfl_u32(pl[0], src1);
            const uint32_t u1l = shfl_u32(pl[1], src1);
            const uint32_t u2l = shfl_u32(pl[2], src1);

            const uint32_t a0h = (t == 0) ? s0h : (t == 1) ? s1h : (t == 2) ? s2h : 0u;
            const uint32_t a0l = (t == 0) ? s0l : (t == 1) ? s1l : (t == 2) ? s2l : 0u;
            const uint32_t a1h = (t == 0) ? u0h : (t == 1) ? u1h : (t == 2) ? u2h : 0u;
            const uint32_t a1l = (t == 0) ? u0l : (t == 1) ? u1l : (t == 2) ? u2l : 0u;

            // ---- layer1 per n-tile (3-term split), convert C1 -> layer2 A frags ----
            uint32_t A0h[4], A1h[4], A2h[4], A3h[4];
            uint32_t A0l[4], A1l[4], A2l[4], A3l[4];
            #pragma unroll
            for (int nt = 0; nt < 8; nt++) {
                float c1[4] = {0.f, 0.f, 0.f, 0.f};
                mma_k8(c1, a0h, a1h, w1h[nt]);
                mma_k8(c1, a0h, a1h, w1l[nt]);
                mma_k8(c1, a0l, a1l, w1h[nt]);

                const float v0 = fmaxf(c1[0] + b1v[nt].x, 0.0f);
                const float v1 = fmaxf(c1[1] + b1v[nt].y, 0.0f);
                const float v2 = fmaxf(c1[2] + b1v[nt].x, 0.0f);
                const float v3 = fmaxf(c1[3] + b1v[nt].y, 0.0f);

                const int kt = nt >> 1;
                if ((nt & 1) == 0) {
                    split_pair(v0, v1, A0h[kt], A0l[kt]);   // (row g,   k 16kt+2t)
                    split_pair(v2, v3, A1h[kt], A1l[kt]);   // (row g+8, k 16kt+2t)
                } else {
                    split_pair(v0, v1, A2h[kt], A2l[kt]);   // (row g,   k 16kt+8+2t)
                    split_pair(v2, v3, A3h[kt], A3l[kt]);   // (row g+8, k 16kt+8+2t)
                }
            }

            // ---- layer2: 4 n-tiles x 4 k-tiles x 3 terms ----
            float C2[4][4];
            #pragma unroll
            for (int nt = 0; nt < 4; nt++) {
                C2[nt][0] = 0.f; C2[nt][1] = 0.f; C2[nt][2] = 0.f; C2[nt][3] = 0.f;
            }
            #pragma unroll
            for (int kt = 0; kt < 4; kt++) {
                #pragma unroll
                for (int nt = 0; nt < 4; nt++) {
                    mma_k16(C2[nt], A0h[kt], A1h[kt], A2h[kt], A3h[kt],
                            bh0[nt][kt], bh1[nt][kt]);
                    mma_k16(C2[nt], A0h[kt], A1h[kt], A2h[kt], A3h[kt],
                            bl0[nt][kt], bl1[nt][kt]);
                    mma_k16(C2[nt], A0l[kt], A1l[kt], A2l[kt], A3l[kt],
                            bh0[nt][kt], bh1[nt][kt]);
                }
            }

            // ---- epilogue: +b2, relu, dot W3 over this lane's 8 cols; quad-reduce ----
            float pA = 0.f, pB = 0.f;
            #pragma unroll
            for (int nt = 0; nt < 4; nt++) {
                const float v0 = fmaxf(C2[nt][0] + b2v[nt].x, 0.0f);
                const float v1 = fmaxf(C2[nt][1] + b2v[nt].y, 0.0f);
                const float v2 = fmaxf(C2[nt][2] + b2v[nt].x, 0.0f);
                const float v3 = fmaxf(C2[nt][3] + b2v[nt].y, 0.0f);
                pA = fmaf(v0, w3v[nt].x, fmaf(v1, w3v[nt].y, pA));
                pB = fmaf(v2, w3v[nt].x, fmaf(v3, w3v[nt].y, pB));
            }
            pA += __shfl_xor_sync(0xFFFFFFFFu, pA, 1);
            pA += __shfl_xor_sync(0xFFFFFFFFu, pA, 2);
            pB += __shfl_xor_sync(0xFFFFFFFFu, pB, 1);
            pB += __shfl_xor_sync(0xFFFFFFFFu, pB, 2);
            if (t == 0) {
                out[row0 + 16 * mt + g]     = pA + b3v;
                out[row0 + 16 * mt + g + 8] = pB + b3v;
            }
        }
    }
}

extern "C" void kernel_launch(void* const* d_in, const int* in_sizes, int n_in,
                              void* d_out, int out_size)
{
    const float* x    = (const float*)d_in[0];
    const float* ln_w = (const float*)d_in[1];
    const float* ln_b = (const float*)d_in[2];
    const float* W1   = (const float*)d_in[3];
    const float* b1   = (const float*)d_in[4];
    const float* W2   = (const float*)d_in[5];
    const float* b2   = (const float*)d_in[6];
    const float* W3   = (const float*)d_in[7];
    const float* b3   = (const float*)d_in[8];
    float* out = (float*)d_out;

    const int n_rows = out_size;                    // 2,097,152
    const int blocks = n_rows / ROWS_PER_CTA;       // 2048, exact

    router_kernel<<<blocks, TPB>>>(x, ln_w, ln_b, W1, b1, W2, b2, W3, b3,
                                   out, n_rows);
}

// round 9
// speedup vs baseline: 4.5257x; 1.3044x over previous
#include <cuda_runtime.h>
#include <cuda_fp16.h>
#include <cstdint>

#define NUM_LAYERS 24
#define LN_EPS 1e-5f
#define TPB 128
#define WARPS 4
#define CHUNKS_PER_WARP 8
#define ROWS_PER_CTA (WARPS * CHUNKS_PER_WARP * 32)   // 1024

// pack {a -> low 16, b -> high 16} as f16x2
static __device__ __forceinline__ uint32_t h2_of(float a, float b) {
    __half2 h = __floats2half2_rn(a, b);
    return *reinterpret_cast<uint32_t*>(&h);
}

// split (a,b) into fp16 pair hi2 and residual pair lo2 (a in low half)
static __device__ __forceinline__ void split_pair_h(float a, float b,
                                                    uint32_t& hi2, uint32_t& lo2) {
    __half2 h = __floats2half2_rn(a, b);
    float2 f = __half22float2(h);
    __half2 l = __floats2half2_rn(a - f.x, b - f.y);
    hi2 = *reinterpret_cast<uint32_t*>(&h);
    lo2 = *reinterpret_cast<uint32_t*>(&l);
}

// D += A @ B  (m16n8k16, f16 in, f32 accum)
static __device__ __forceinline__ void mma_k16(
    float* c, uint32_t a0, uint32_t a1, uint32_t a2, uint32_t a3,
    uint32_t b0, uint32_t b1)
{
    asm volatile(
        "mma.sync.aligned.m16n8k16.row.col.f32.f16.f16.f32 "
        "{%0,%1,%2,%3}, {%4,%5,%6,%7}, {%8,%9}, {%0,%1,%2,%3};"
        : "+f"(c[0]), "+f"(c[1]), "+f"(c[2]), "+f"(c[3])
        : "r"(a0), "r"(a1), "r"(a2), "r"(a3), "r"(b0), "r"(b1));
}

// D += A @ B  (m16n8k8, f16 in, f32 accum)
static __device__ __forceinline__ void mma_k8(
    float* c, uint32_t a0, uint32_t a1, uint32_t b0)
{
    asm volatile(
        "mma.sync.aligned.m16n8k8.row.col.f32.f16.f16.f32 "
        "{%0,%1,%2,%3}, {%4,%5}, {%6}, {%0,%1,%2,%3};"
        : "+f"(c[0]), "+f"(c[1]), "+f"(c[2]), "+f"(c[3])
        : "r"(a0), "r"(a1), "r"(b0));
}

static __device__ __forceinline__ uint32_t shfl_u32(uint32_t v, int src) {
    return __shfl_sync(0xFFFFFFFFu, v, src);
}

__global__ __launch_bounds__(TPB) void router_kernel(
    const float* __restrict__ x,
    const float* __restrict__ ln_w,
    const float* __restrict__ ln_b,
    const float* __restrict__ W1,
    const float* __restrict__ b1,
    const float* __restrict__ W2,
    const float* __restrict__ b2,
    const float* __restrict__ W3,
    const float* __restrict__ b3,
    float* __restrict__ out,
    int n_rows)
{
    __shared__ float sLnW[NUM_LAYERS * 4];
    __shared__ float sLnB[NUM_LAYERS * 4];

    const int tid  = threadIdx.x;
    const int lane = tid & 31;
    const int warp = tid >> 5;
    const int g = lane >> 2;     // 0..7
    const int t = lane & 3;      // 0..3

    if (tid < NUM_LAYERS * 4) { sLnW[tid] = ln_w[tid]; sLnB[tid] = ln_b[tid]; }
    __syncthreads();

    // ---- W1 B-fragments (m16n8k8, 8 n-tiles), fp16 2-term split; k = 2t,2t+1 ----
    uint32_t w1h[8], w1l[8];
    #pragma unroll
    for (int nt = 0; nt < 8; nt++) {
        const float* wr = W1 + (8 * nt + g) * 5;
        const float w0 = (2 * t     < 5) ? wr[2 * t]     : 0.0f;
        const float w1v = (2 * t + 1 < 5) ? wr[2 * t + 1] : 0.0f;
        split_pair_h(w0, w1v, w1h[nt], w1l[nt]);
    }

    // ---- W2 B-fragments (m16n8k16, 4 n-tiles x 4 k-tiles), fp16 2-term split ----
    uint32_t bh0[4][4], bh1[4][4], bl0[4][4], bl1[4][4];
    #pragma unroll
    for (int nt = 0; nt < 4; nt++) {
        #pragma unroll
        for (int kt = 0; kt < 4; kt++) {
            const float* wrow = W2 + (8 * nt + g) * 64 + 16 * kt + 2 * t;
            const float2 w0 = *reinterpret_cast<const float2*>(wrow);
            const float2 w1v = *reinterpret_cast<const float2*>(wrow + 8);
            split_pair_h(w0.x, w0.y, bh0[nt][kt], bl0[nt][kt]);
            split_pair_h(w1v.x, w1v.y, bh1[nt][kt], bl1[nt][kt]);
        }
    }

    // per-lane bias/weight pairs for this lane's columns
    float2 b1v[8];
    #pragma unroll
    for (int nt = 0; nt < 8; nt++)
        b1v[nt] = *reinterpret_cast<const float2*>(b1 + 8 * nt + 2 * t);
    float2 b2v[4], w3v[4];
    #pragma unroll
    for (int nt = 0; nt < 4; nt++) {
        b2v[nt] = *reinterpret_cast<const float2*>(b2 + 8 * nt + 2 * t);
        w3v[nt] = *reinterpret_cast<const float2*>(W3 + 8 * nt + 2 * t);
    }
    const float b3v = b3[0];

    const long long warp_row0 = (long long)blockIdx.x * ROWS_PER_CTA
                              + (long long)warp * (CHUNKS_PER_WARP * 32);

    for (int ch = 0; ch < CHUNKS_PER_WARP; ch++) {
        const long long row0 = warp_row0 + ch * 32;

        // ---- scalar LN for row = row0 + lane ----
        const float* xr = x + (row0 + lane) * 5;
        const float f0 = xr[0], f1 = xr[1], f2 = xr[2], f3 = xr[3], pos = xr[4];

        const float mean = (f0 + f1 + f2 + f3) * 0.25f;
        const float d0 = f0 - mean, d1 = f1 - mean, d2 = f2 - mean, d3 = f3 - mean;
        const float var  = (d0 * d0 + d1 * d1 + d2 * d2 + d3 * d3) * 0.25f;
        const float rstd = rsqrtf(var + LN_EPS);

        int lid = (int)(pos * (float)NUM_LAYERS);
        lid = max(0, min(NUM_LAYERS - 1, lid));

        const float n0 = d0 * rstd * sLnW[lid * 4 + 0] + sLnB[lid * 4 + 0];
        const float n1 = d1 * rstd * sLnW[lid * 4 + 1] + sLnB[lid * 4 + 1];
        const float n2 = d2 * rstd * sLnW[lid * 4 + 2] + sLnB[lid * 4 + 2];
        const float n3 = d3 * rstd * sLnW[lid * 4 + 3] + sLnB[lid * 4 + 3];

        // feature pairs (this lane's row), single fp16: {n0,n1},{n2,n3},{pos,0}
        uint32_t ph[3];
        ph[0] = h2_of(n0, n1);
        ph[1] = h2_of(n2, n3);
        ph[2] = h2_of(pos, 0.0f);

        #pragma unroll
        for (int mt = 0; mt < 2; mt++) {
            const int src0 = 16 * mt + g;       // row for a0
            const int src1 = src0 + 8;          // row for a1

            // transpose features via shuffle (6 shfl), then per-lane k-select
            const uint32_t s0 = shfl_u32(ph[0], src0);
            const uint32_t s1 = shfl_u32(ph[1], src0);
            const uint32_t s2 = shfl_u32(ph[2], src0);
            const uint32_t u0 = shfl_u32(ph[0], src1);
            const uint32_t u1 = shfl_u32(ph[1], src1);
            const uint32_t u2 = shfl_u32(ph[2], src1);

            const uint32_t a0 = (t == 0) ? s0 : (t == 1) ? s1 : (t == 2) ? s2 : 0u;
            const uint32_t a1 = (t == 0) ? u0 : (t == 1) ? u1 : (t == 2) ? u2 : 0u;

            // ---- layer1 per n-tile (2 products: A·W1h + A·W1l), C1 -> layer2 A frags ----
            uint32_t A0[4], A1[4], A2[4], A3[4];
            #pragma unroll
            for (int nt = 0; nt < 8; nt++) {
                float c1[4] = {0.f, 0.f, 0.f, 0.f};
                mma_k8(c1, a0, a1, w1h[nt]);
                mma_k8(c1, a0, a1, w1l[nt]);

                const float v0 = fmaxf(c1[0] + b1v[nt].x, 0.0f);
                const float v1 = fmaxf(c1[1] + b1v[nt].y, 0.0f);
                const float v2 = fmaxf(c1[2] + b1v[nt].x, 0.0f);
                const float v3 = fmaxf(c1[3] + b1v[nt].y, 0.0f);

                const int kt = nt >> 1;
                if ((nt & 1) == 0) {
                    A0[kt] = h2_of(v0, v1);   // (row g,   k 16kt+2t,2t+1)
                    A1[kt] = h2_of(v2, v3);   // (row g+8, k 16kt+2t,2t+1)
                } else {
                    A2[kt] = h2_of(v0, v1);   // (row g,   k 16kt+8+2t)
                    A3[kt] = h2_of(v2, v3);   // (row g+8, k 16kt+8+2t)
                }
            }

            // ---- layer2: 4 n-tiles x 4 k-tiles x 2 products ----
            float C2[4][4];
            #pragma unroll
            for (int nt = 0; nt < 4; nt++) {
                C2[nt][0] = 0.f; C2[nt][1] = 0.f; C2[nt][2] = 0.f; C2[nt][3] = 0.f;
            }
            #pragma unroll
            for (int kt = 0; kt < 4; kt++) {
                #pragma unroll
                for (int nt = 0; nt < 4; nt++) {
                    mma_k16(C2[nt], A0[kt], A1[kt], A2[kt], A3[kt],
                            bh0[nt][kt], bh1[nt][kt]);
                    mma_k16(C2[nt], A0[kt], A1[kt], A2[kt], A3[kt],
                            bl0[nt][kt], bl1[nt][kt]);
                }
            }

            // ---- epilogue: +b2, relu, dot W3 over this lane's 8 cols; quad-reduce ----
            float pA = 0.f, pB = 0.f;
            #pragma unroll
            for (int nt = 0; nt < 4; nt++) {
                const float v0 = fmaxf(C2[nt][0] + b2v[nt].x, 0.0f);
                const float v1 = fmaxf(C2[nt][1] + b2v[nt].y, 0.0f);
                const float v2 = fmaxf(C2[nt][2] + b2v[nt].x, 0.0f);
                const float v3 = fmaxf(C2[nt][3] + b2v[nt].y, 0.0f);
                pA = fmaf(v0, w3v[nt].x, fmaf(v1, w3v[nt].y, pA));
                pB = fmaf(v2, w3v[nt].x, fmaf(v3, w3v[nt].y, pB));
            }
            pA += __shfl_xor_sync(0xFFFFFFFFu, pA, 1);
            pA += __shfl_xor_sync(0xFFFFFFFFu, pA, 2);
            pB += __shfl_xor_sync(0xFFFFFFFFu, pB, 1);
            pB += __shfl_xor_sync(0xFFFFFFFFu, pB, 2);
            if (t == 0) {
                out[row0 + 16 * mt + g]     = pA + b3v;
                out[row0 + 16 * mt + g + 8] = pB + b3v;
            }
        }
    }
}

extern "C" void kernel_launch(void* const* d_in, const int* in_sizes, int n_in,
                              void* d_out, int out_size)
{
    const float* x    = (const float*)d_in[0];
    const float* ln_w = (const float*)d_in[1];
    const float* ln_b = (const float*)d_in[2];
    const float* W1   = (const float*)d_in[3];
    const float* b1   = (const float*)d_in[4];
    const float* W2   = (const float*)d_in[5];
    const float* b2   = (const float*)d_in[6];
    const float* W3   = (const float*)d_in[7];
    const float* b3   = (const float*)d_in[8];
    float* out = (float*)d_out;

    const int n_rows = out_size;                    // 2,097,152
    const int blocks = n_rows / ROWS_PER_CTA;       // 2048, exact

    router_kernel<<<blocks, TPB>>>(x, ln_w, ln_b, W1, b1, W2, b2, W3, b3,
                                   out, n_rows);
}

// round 10
// speedup vs baseline: 4.8463x; 1.0708x over previous
#include <cuda_runtime.h>
#include <cuda_fp16.h>
#include <cstdint>

#define NUM_LAYERS 24
#define LN_EPS 1e-5f
#define TPB 128
#define WARPS 4
#define CHUNKS_PER_WARP 8
#define ROWS_PER_CTA (WARPS * CHUNKS_PER_WARP * 32)   // 1024

// pack {a -> low 16, b -> high 16} as f16x2
static __device__ __forceinline__ uint32_t h2_of(float a, float b) {
    __half2 h = __floats2half2_rn(a, b);
    return *reinterpret_cast<uint32_t*>(&h);
}

// split (a,b) into fp16 pair hi2 and residual pair lo2 (a in low half)
static __device__ __forceinline__ void split_pair_h(float a, float b,
                                                    uint32_t& hi2, uint32_t& lo2) {
    __half2 h = __floats2half2_rn(a, b);
    float2 f = __half22float2(h);
    __half2 l = __floats2half2_rn(a - f.x, b - f.y);
    hi2 = *reinterpret_cast<uint32_t*>(&h);
    lo2 = *reinterpret_cast<uint32_t*>(&l);
}

// D += A @ B  (m16n8k16, f16 in, f32 accum)
static __device__ __forceinline__ void mma_k16(
    float* c, uint32_t a0, uint32_t a1, uint32_t a2, uint32_t a3,
    uint32_t b0, uint32_t b1)
{
    asm volatile(
        "mma.sync.aligned.m16n8k16.row.col.f32.f16.f16.f32 "
        "{%0,%1,%2,%3}, {%4,%5,%6,%7}, {%8,%9}, {%0,%1,%2,%3};"
        : "+f"(c[0]), "+f"(c[1]), "+f"(c[2]), "+f"(c[3])
        : "r"(a0), "r"(a1), "r"(a2), "r"(a3), "r"(b0), "r"(b1));
}

// D += A @ B  (m16n8k8, f16 in, f32 accum)
static __device__ __forceinline__ void mma_k8(
    float* c, uint32_t a0, uint32_t a1, uint32_t b0)
{
    asm volatile(
        "mma.sync.aligned.m16n8k8.row.col.f32.f16.f16.f32 "
        "{%0,%1,%2,%3}, {%4,%5}, {%6}, {%0,%1,%2,%3};"
        : "+f"(c[0]), "+f"(c[1]), "+f"(c[2]), "+f"(c[3])
        : "r"(a0), "r"(a1), "r"(b0));
}

static __device__ __forceinline__ uint32_t shfl_u32(uint32_t v, int src) {
    return __shfl_sync(0xFFFFFFFFu, v, src);
}

__global__ __launch_bounds__(TPB, 4) void router_kernel(
    const float* __restrict__ x,
    const float* __restrict__ ln_w,
    const float* __restrict__ ln_b,
    const float* __restrict__ W1,
    const float* __restrict__ b1,
    const float* __restrict__ W2,
    const float* __restrict__ b2,
    const float* __restrict__ W3,
    const float* __restrict__ b3,
    float* __restrict__ out,
    int n_rows)
{
    __shared__ float sLnW[NUM_LAYERS * 4];
    __shared__ float sLnB[NUM_LAYERS * 4];
    // W2 fragments: [term(4: bh0,bh1,bl0,bl1)][nt*4+kt(16)][lane(32)] — lane-consecutive
    __shared__ uint32_t sW2[4 * 16 * 32];

    const int tid  = threadIdx.x;
    const int lane = tid & 31;
    const int warp = tid >> 5;
    const int g = lane >> 2;     // 0..7
    const int t = lane & 3;      // 0..3

    if (tid < NUM_LAYERS * 4) { sLnW[tid] = ln_w[tid]; sLnB[tid] = ln_b[tid]; }

    // ---- build W2 fragment table in shared (identical across warps) ----
    for (int i = tid; i < 4 * 16 * 32; i += TPB) {
        const int l    = i & 31;
        const int ntkt = (i >> 5) & 15;
        const int p    = i >> 9;             // 0:bh0 1:bh1 2:bl0 3:bl1
        const int gg = l >> 2, tt = l & 3;
        const int nt = ntkt >> 2, kt = ntkt & 3;
        const float* wrow = W2 + (8 * nt + gg) * 64 + 16 * kt + 2 * tt + ((p & 1) ? 8 : 0);
        uint32_t hi, lo;
        split_pair_h(wrow[0], wrow[1], hi, lo);
        sW2[i] = (p < 2) ? hi : lo;
    }
    __syncthreads();

    // ---- W1 B-fragments (single fp16, m16n8k8, 8 n-tiles); k = 2t,2t+1 (>=5 -> 0) ----
    uint32_t w1h[8];
    #pragma unroll
    for (int nt = 0; nt < 8; nt++) {
        const float* wr = W1 + (8 * nt + g) * 5;
        const float w0 = (2 * t     < 5) ? wr[2 * t]     : 0.0f;
        const float w1v = (2 * t + 1 < 5) ? wr[2 * t + 1] : 0.0f;
        w1h[nt] = h2_of(w0, w1v);
    }

    // per-lane bias/weight pairs for this lane's columns
    float2 b1v[8];
    #pragma unroll
    for (int nt = 0; nt < 8; nt++)
        b1v[nt] = *reinterpret_cast<const float2*>(b1 + 8 * nt + 2 * t);
    float2 b2v[4], w3v[4];
    #pragma unroll
    for (int nt = 0; nt < 4; nt++) {
        b2v[nt] = *reinterpret_cast<const float2*>(b2 + 8 * nt + 2 * t);
        w3v[nt] = *reinterpret_cast<const float2*>(W3 + 8 * nt + 2 * t);
    }
    const float b3v = b3[0];

    const long long warp_row0 = (long long)blockIdx.x * ROWS_PER_CTA
                              + (long long)warp * (CHUNKS_PER_WARP * 32);
    const float* xbase = x + (warp_row0 + lane) * 5;

    // preload chunk 0's row
    float cx0 = xbase[0], cx1 = xbase[1], cx2 = xbase[2], cx3 = xbase[3], cx4 = xbase[4];

    for (int ch = 0; ch < CHUNKS_PER_WARP; ch++) {
        const long long row0 = warp_row0 + ch * 32;

        // ---- prefetch next chunk's row (last chunk: harmless reload of current) ----
        const float* xn = xbase + ((ch + 1 < CHUNKS_PER_WARP) ? (ch + 1) : ch) * (32 * 5);
        const float nx0 = xn[0], nx1 = xn[1], nx2 = xn[2], nx3 = xn[3], nx4 = xn[4];

        // ---- scalar LN for row = row0 + lane ----
        const float f0 = cx0, f1 = cx1, f2 = cx2, f3 = cx3, pos = cx4;

        const float mean = (f0 + f1 + f2 + f3) * 0.25f;
        const float d0 = f0 - mean, d1 = f1 - mean, d2 = f2 - mean, d3 = f3 - mean;
        const float var  = (d0 * d0 + d1 * d1 + d2 * d2 + d3 * d3) * 0.25f;
        const float rstd = rsqrtf(var + LN_EPS);

        int lid = (int)(pos * (float)NUM_LAYERS);
        lid = max(0, min(NUM_LAYERS - 1, lid));

        const float n0 = d0 * rstd * sLnW[lid * 4 + 0] + sLnB[lid * 4 + 0];
        const float n1 = d1 * rstd * sLnW[lid * 4 + 1] + sLnB[lid * 4 + 1];
        const float n2 = d2 * rstd * sLnW[lid * 4 + 2] + sLnB[lid * 4 + 2];
        const float n3 = d3 * rstd * sLnW[lid * 4 + 3] + sLnB[lid * 4 + 3];

        // feature pairs (this lane's row), single fp16: {n0,n1},{n2,n3},{pos,0}
        uint32_t ph[3];
        ph[0] = h2_of(n0, n1);
        ph[1] = h2_of(n2, n3);
        ph[2] = h2_of(pos, 0.0f);

        #pragma unroll
        for (int mt = 0; mt < 2; mt++) {
            const int src0 = 16 * mt + g;       // row for a0
            const int src1 = src0 + 8;          // row for a1

            // transpose features via shuffle (6 shfl), then per-lane k-select
            const uint32_t s0 = shfl_u32(ph[0], src0);
            const uint32_t s1 = shfl_u32(ph[1], src0);
            const uint32_t s2 = shfl_u32(ph[2], src0);
            const uint32_t u0 = shfl_u32(ph[0], src1);
            const uint32_t u1 = shfl_u32(ph[1], src1);
            const uint32_t u2 = shfl_u32(ph[2], src1);

            const uint32_t a0 = (t == 0) ? s0 : (t == 1) ? s1 : (t == 2) ? s2 : 0u;
            const uint32_t a1 = (t == 0) ? u0 : (t == 1) ? u1 : (t == 2) ? u2 : 0u;

            // ---- layer1 per n-tile (single product), C1 -> layer2 A frags ----
            uint32_t A0[4], A1[4], A2[4], A3[4];
            #pragma unroll
            for (int nt = 0; nt < 8; nt++) {
                float c1[4] = {0.f, 0.f, 0.f, 0.f};
                mma_k8(c1, a0, a1, w1h[nt]);

                const float v0 = fmaxf(c1[0] + b1v[nt].x, 0.0f);
                const float v1 = fmaxf(c1[1] + b1v[nt].y, 0.0f);
                const float v2 = fmaxf(c1[2] + b1v[nt].x, 0.0f);
                const float v3 = fmaxf(c1[3] + b1v[nt].y, 0.0f);

                const int kt = nt >> 1;
                if ((nt & 1) == 0) {
                    A0[kt] = h2_of(v0, v1);   // (row g,   k 16kt+2t,2t+1)
                    A1[kt] = h2_of(v2, v3);   // (row g+8, k 16kt+2t,2t+1)
                } else {
                    A2[kt] = h2_of(v0, v1);   // (row g,   k 16kt+8+2t)
                    A3[kt] = h2_of(v2, v3);   // (row g+8, k 16kt+8+2t)
                }
            }

            // ---- layer2: 4 n-tiles x 4 k-tiles x 2 products (frags from smem) ----
            float C2[4][4];
            #pragma unroll
            for (int nt = 0; nt < 4; nt++) {
                C2[nt][0] = 0.f; C2[nt][1] = 0.f; C2[nt][2] = 0.f; C2[nt][3] = 0.f;
            }
            #pragma unroll
            for (int kt = 0; kt < 4; kt++) {
                #pragma unroll
                for (int nt = 0; nt < 4; nt++) {
                    const int base = (nt * 4 + kt) * 32 + lane;
                    mma_k16(C2[nt], A0[kt], A1[kt], A2[kt], A3[kt],
                            sW2[base], sW2[512 + base]);
                    mma_k16(C2[nt], A0[kt], A1[kt], A2[kt], A3[kt],
                            sW2[1024 + base], sW2[1536 + base]);
                }
            }

            // ---- epilogue: +b2, relu, dot W3 over this lane's 8 cols; quad-reduce ----
            float pA = 0.f, pB = 0.f;
            #pragma unroll
            for (int nt = 0; nt < 4; nt++) {
                const float v0 = fmaxf(C2[nt][0] + b2v[nt].x, 0.0f);
                const float v1 = fmaxf(C2[nt][1] + b2v[nt].y, 0.0f);
                const float v2 = fmaxf(C2[nt][2] + b2v[nt].x, 0.0f);
                const float v3 = fmaxf(C2[nt][3] + b2v[nt].y, 0.0f);
                pA = fmaf(v0, w3v[nt].x, fmaf(v1, w3v[nt].y, pA));
                pB = fmaf(v2, w3v[nt].x, fmaf(v3, w3v[nt].y, pB));
            }
            pA += __shfl_xor_sync(0xFFFFFFFFu, pA, 1);
            pA += __shfl_xor_sync(0xFFFFFFFFu, pA, 2);
            pB += __shfl_xor_sync(0xFFFFFFFFu, pB, 1);
            pB += __shfl_xor_sync(0xFFFFFFFFu, pB, 2);
            if (t == 0) {
                out[row0 + 16 * mt + g]     = pA + b3v;
                out[row0 + 16 * mt + g + 8] = pB + b3v;
            }
        }

        // rotate prefetched row into current
        cx0 = nx0; cx1 = nx1; cx2 = nx2; cx3 = nx3; cx4 = nx4;
    }
}

extern "C" void kernel_launch(void* const* d_in, const int* in_sizes, int n_in,
                              void* d_out, int out_size)
{
    const float* x    = (const float*)d_in[0];
    const float* ln_w = (const float*)d_in[1];
    const float* ln_b = (const float*)d_in[2];
    const float* W1   = (const float*)d_in[3];
    const float* b1   = (const float*)d_in[4];
    const float* W2   = (const float*)d_in[5];
    const float* b2   = (const float*)d_in[6];
    const float* W3   = (const float*)d_in[7];
    const float* b3   = (const float*)d_in[8];
    float* out = (float*)d_out;

    const int n_rows = out_size;                    // 2,097,152
    const int blocks = n_rows / ROWS_PER_CTA;       // 2048, exact

    router_kernel<<<blocks, TPB>>>(x, ln_w, ln_b, W1, b1, W2, b2, W3, b3,
                                   out, n_rows);
}

// round 11
// speedup vs baseline: 7.0468x; 1.4541x over previous
#include <cuda_runtime.h>
#include <cuda_fp16.h>
#include <cstdint>

#define NUM_LAYERS 24
#define LN_EPS 1e-5f
#define TPB 128
#define WARPS 4
#define CHUNKS_PER_WARP 8
#define ROWS_PER_CTA (WARPS * CHUNKS_PER_WARP * 32)   // 1024

// pack {a -> low 16, b -> high 16} as f16x2
static __device__ __forceinline__ uint32_t h2_of(float a, float b) {
    __half2 h = __floats2half2_rn(a, b);
    return *reinterpret_cast<uint32_t*>(&h);
}

// D += A @ B  (m16n8k16, f16 in, f32 accum)
static __device__ __forceinline__ void mma_k16(
    float* c, uint32_t a0, uint32_t a1, uint32_t a2, uint32_t a3,
    uint32_t b0, uint32_t b1)
{
    asm volatile(
        "mma.sync.aligned.m16n8k16.row.col.f32.f16.f16.f32 "
        "{%0,%1,%2,%3}, {%4,%5,%6,%7}, {%8,%9}, {%0,%1,%2,%3};"
        : "+f"(c[0]), "+f"(c[1]), "+f"(c[2]), "+f"(c[3])
        : "r"(a0), "r"(a1), "r"(a2), "r"(a3), "r"(b0), "r"(b1));
}

// D += A @ B  (m16n8k8, f16 in, f32 accum)
static __device__ __forceinline__ void mma_k8(
    float* c, uint32_t a0, uint32_t a1, uint32_t b0)
{
    asm volatile(
        "mma.sync.aligned.m16n8k8.row.col.f32.f16.f16.f32 "
        "{%0,%1,%2,%3}, {%4,%5}, {%6}, {%0,%1,%2,%3};"
        : "+f"(c[0]), "+f"(c[1]), "+f"(c[2]), "+f"(c[3])
        : "r"(a0), "r"(a1), "r"(b0));
}

static __device__ __forceinline__ uint32_t shfl_u32(uint32_t v, int src) {
    return __shfl_sync(0xFFFFFFFFu, v, src);
}

__global__ __launch_bounds__(TPB, 4) void router_kernel(
    const float* __restrict__ x,
    const float* __restrict__ ln_w,
    const float* __restrict__ ln_b,
    const float* __restrict__ W1,
    const float* __restrict__ b1,
    const float* __restrict__ W2,
    const float* __restrict__ b2,
    const float* __restrict__ W3,
    const float* __restrict__ b3,
    float* __restrict__ out,
    int n_rows)
{
    __shared__ float sLnW[NUM_LAYERS * 4];
    __shared__ float sLnB[NUM_LAYERS * 4];
    // W2 fragments (single fp16): [half(2: b0,b1)][nt*4+kt(16)][lane(32)]
    __shared__ uint32_t sW2[2 * 16 * 32];

    const int tid  = threadIdx.x;
    const int lane = tid & 31;
    const int warp = tid >> 5;
    const int g = lane >> 2;     // 0..7
    const int t = lane & 3;      // 0..3

    if (tid < NUM_LAYERS * 4) { sLnW[tid] = ln_w[tid]; sLnB[tid] = ln_b[tid]; }

    // ---- build W2 fragment table in shared (identical across warps) ----
    for (int i = tid; i < 2 * 16 * 32; i += TPB) {
        const int l    = i & 31;
        const int ntkt = (i >> 5) & 15;
        const int p    = i >> 9;             // 0: b0 (k+0), 1: b1 (k+8)
        const int gg = l >> 2, tt = l & 3;
        const int nt = ntkt >> 2, kt = ntkt & 3;
        const float* wrow = W2 + (8 * nt + gg) * 64 + 16 * kt + 2 * tt + (p ? 8 : 0);
        sW2[i] = h2_of(wrow[0], wrow[1]);
    }
    __syncthreads();

    // ---- W1 B-fragments (single fp16, m16n8k8, 8 n-tiles); k = 2t,2t+1 (>=5 -> 0) ----
    uint32_t w1h[8];
    #pragma unroll
    for (int nt = 0; nt < 8; nt++) {
        const float* wr = W1 + (8 * nt + g) * 5;
        const float w0 = (2 * t     < 5) ? wr[2 * t]     : 0.0f;
        const float w1v = (2 * t + 1 < 5) ? wr[2 * t + 1] : 0.0f;
        w1h[nt] = h2_of(w0, w1v);
    }

    // per-lane bias/weight pairs for this lane's columns
    float2 b1v[8];
    #pragma unroll
    for (int nt = 0; nt < 8; nt++)
        b1v[nt] = *reinterpret_cast<const float2*>(b1 + 8 * nt + 2 * t);
    float2 b2v[4], w3v[4];
    #pragma unroll
    for (int nt = 0; nt < 4; nt++) {
        b2v[nt] = *reinterpret_cast<const float2*>(b2 + 8 * nt + 2 * t);
        w3v[nt] = *reinterpret_cast<const float2*>(W3 + 8 * nt + 2 * t);
    }
    const float b3v = b3[0];

    const long long warp_row0 = (long long)blockIdx.x * ROWS_PER_CTA
                              + (long long)warp * (CHUNKS_PER_WARP * 32);
    const float* xbase = x + (warp_row0 + lane) * 5;

    // preload chunk 0's row
    float cx0 = xbase[0], cx1 = xbase[1], cx2 = xbase[2], cx3 = xbase[3], cx4 = xbase[4];

    for (int ch = 0; ch < CHUNKS_PER_WARP; ch++) {
        const long long row0 = warp_row0 + ch * 32;

        // ---- prefetch next chunk's row (last chunk: harmless reload of current) ----
        const float* xn = xbase + ((ch + 1 < CHUNKS_PER_WARP) ? (ch + 1) : ch) * (32 * 5);
        const float nx0 = xn[0], nx1 = xn[1], nx2 = xn[2], nx3 = xn[3], nx4 = xn[4];

        // ---- scalar LN for row = row0 + lane ----
        const float f0 = cx0, f1 = cx1, f2 = cx2, f3 = cx3, pos = cx4;

        const float mean = (f0 + f1 + f2 + f3) * 0.25f;
        const float d0 = f0 - mean, d1 = f1 - mean, d2 = f2 - mean, d3 = f3 - mean;
        const float var  = (d0 * d0 + d1 * d1 + d2 * d2 + d3 * d3) * 0.25f;
        const float rstd = rsqrtf(var + LN_EPS);

        int lid = (int)(pos * (float)NUM_LAYERS);
        lid = max(0, min(NUM_LAYERS - 1, lid));

        const float n0 = d0 * rstd * sLnW[lid * 4 + 0] + sLnB[lid * 4 + 0];
        const float n1 = d1 * rstd * sLnW[lid * 4 + 1] + sLnB[lid * 4 + 1];
        const float n2 = d2 * rstd * sLnW[lid * 4 + 2] + sLnB[lid * 4 + 2];
        const float n3 = d3 * rstd * sLnW[lid * 4 + 3] + sLnB[lid * 4 + 3];

        // feature pairs (this lane's row), single fp16: {n0,n1},{n2,n3},{pos,0}
        uint32_t ph[3];
        ph[0] = h2_of(n0, n1);
        ph[1] = h2_of(n2, n3);
        ph[2] = h2_of(pos, 0.0f);

        #pragma unroll
        for (int mt = 0; mt < 2; mt++) {
            const int src0 = 16 * mt + g;       // row for a0
            const int src1 = src0 + 8;          // row for a1

            // transpose features via shuffle (6 shfl), then per-lane k-select
            const uint32_t s0 = shfl_u32(ph[0], src0);
            const uint32_t s1 = shfl_u32(ph[1], src0);
            const uint32_t s2 = shfl_u32(ph[2], src0);
            const uint32_t u0 = shfl_u32(ph[0], src1);
            const uint32_t u1 = shfl_u32(ph[1], src1);
            const uint32_t u2 = shfl_u32(ph[2], src1);

            const uint32_t a0 = (t == 0) ? s0 : (t == 1) ? s1 : (t == 2) ? s2 : 0u;
            const uint32_t a1 = (t == 0) ? u0 : (t == 1) ? u1 : (t == 2) ? u2 : 0u;

            // ---- layer1 per n-tile (single product), C1 -> layer2 A frags ----
            uint32_t A0[4], A1[4], A2[4], A3[4];
            #pragma unroll
            for (int nt = 0; nt < 8; nt++) {
                float c1[4] = {0.f, 0.f, 0.f, 0.f};
                mma_k8(c1, a0, a1, w1h[nt]);

                const float v0 = fmaxf(c1[0] + b1v[nt].x, 0.0f);
                const float v1 = fmaxf(c1[1] + b1v[nt].y, 0.0f);
                const float v2 = fmaxf(c1[2] + b1v[nt].x, 0.0f);
                const float v3 = fmaxf(c1[3] + b1v[nt].y, 0.0f);

                const int kt = nt >> 1;
                if ((nt & 1) == 0) {
                    A0[kt] = h2_of(v0, v1);   // (row g,   k 16kt+2t,2t+1)
                    A1[kt] = h2_of(v2, v3);   // (row g+8, k 16kt+2t,2t+1)
                } else {
                    A2[kt] = h2_of(v0, v1);   // (row g,   k 16kt+8+2t)
                    A3[kt] = h2_of(v2, v3);   // (row g+8, k 16kt+8+2t)
                }
            }

            // ---- layer2: 4 n-tiles x 4 k-tiles, single fp16 product ----
            float C2[4][4];
            #pragma unroll
            for (int nt = 0; nt < 4; nt++) {
                C2[nt][0] = 0.f; C2[nt][1] = 0.f; C2[nt][2] = 0.f; C2[nt][3] = 0.f;
            }
            #pragma unroll
            for (int kt = 0; kt < 4; kt++) {
                #pragma unroll
                for (int nt = 0; nt < 4; nt++) {
                    const int base = (nt * 4 + kt) * 32 + lane;
                    mma_k16(C2[nt], A0[kt], A1[kt], A2[kt], A3[kt],
                            sW2[base], sW2[512 + base]);
                }
            }

            // ---- epilogue: +b2, relu, dot W3 over this lane's 8 cols; quad-reduce ----
            float pA = 0.f, pB = 0.f;
            #pragma unroll
            for (int nt = 0; nt < 4; nt++) {
                const float v0 = fmaxf(C2[nt][0] + b2v[nt].x, 0.0f);
                const float v1 = fmaxf(C2[nt][1] + b2v[nt].y, 0.0f);
                const float v2 = fmaxf(C2[nt][2] + b2v[nt].x, 0.0f);
                const float v3 = fmaxf(C2[nt][3] + b2v[nt].y, 0.0f);
                pA = fmaf(v0, w3v[nt].x, fmaf(v1, w3v[nt].y, pA));
                pB = fmaf(v2, w3v[nt].x, fmaf(v3, w3v[nt].y, pB));
            }
            pA += __shfl_xor_sync(0xFFFFFFFFu, pA, 1);
            pA += __shfl_xor_sync(0xFFFFFFFFu, pA, 2);
            pB += __shfl_xor_sync(0xFFFFFFFFu, pB, 1);
            pB += __shfl_xor_sync(0xFFFFFFFFu, pB, 2);
            if (t == 0) {
                out[row0 + 16 * mt + g]     = pA + b3v;
                out[row0 + 16 * mt + g + 8] = pB + b3v;
            }
        }

        // rotate prefetched row into current
        cx0 = nx0; cx1 = nx1; cx2 = nx2; cx3 = nx3; cx4 = nx4;
    }
}

extern "C" void kernel_launch(void* const* d_in, const int* in_sizes, int n_in,
                              void* d_out, int out_size)
{
    const float* x    = (const float*)d_in[0];
    const float* ln_w = (const float*)d_in[1];
    const float* ln_b = (const float*)d_in[2];
    const float* W1   = (const float*)d_in[3];
    const float* b1   = (const float*)d_in[4];
    const float* W2   = (const float*)d_in[5];
    const float* b2   = (const float*)d_in[6];
    const float* W3   = (const float*)d_in[7];
    const float* b3   = (const float*)d_in[8];
    float* out = (float*)d_out;

    const int n_rows = out_size;                    // 2,097,152
    const int blocks = n_rows / ROWS_PER_CTA;       // 2048, exact

    router_kernel<<<blocks, TPB>>>(x, ln_w, ln_b, W1, b1, W2, b2, W3, b3,
                                   out, n_rows);
}

// round 12
// speedup vs baseline: 7.7597x; 1.1012x over previous
#include <cuda_runtime.h>
#include <cuda_fp16.h>
#include <cstdint>

#define NUM_LAYERS 24
#define LN_EPS 1e-5f
#define TPB 128
#define WARPS 4
#define CHUNKS_PER_WARP 8
#define ROWS_PER_CTA (WARPS * CHUNKS_PER_WARP * 32)   // 1024

// pack {a -> low 16, b -> high 16} as f16x2
static __device__ __forceinline__ uint32_t h2_of(float a, float b) {
    __half2 h = __floats2half2_rn(a, b);
    return *reinterpret_cast<uint32_t*>(&h);
}

// elementwise max(x, 0) on packed f16x2
static __device__ __forceinline__ uint32_t hmax2_zero(uint32_t v) {
    __half2 h = *reinterpret_cast<__half2*>(&v);
    __half2 z = __half2half2(__ushort_as_half(0));
    __half2 r = __hmax2(h, z);
    return *reinterpret_cast<uint32_t*>(&r);
}

// D += A @ B  (m16n8k16, f16 in, f32 accum)
static __device__ __forceinline__ void mma_k16(
    float* c, uint32_t a0, uint32_t a1, uint32_t a2, uint32_t a3,
    uint32_t b0, uint32_t b1)
{
    asm volatile(
        "mma.sync.aligned.m16n8k16.row.col.f32.f16.f16.f32 "
        "{%0,%1,%2,%3}, {%4,%5,%6,%7}, {%8,%9}, {%0,%1,%2,%3};"
        : "+f"(c[0]), "+f"(c[1]), "+f"(c[2]), "+f"(c[3])
        : "r"(a0), "r"(a1), "r"(a2), "r"(a3), "r"(b0), "r"(b1));
}

// D += A @ B  (m16n8k8, f16 in, f32 accum)
static __device__ __forceinline__ void mma_k8(
    float* c, uint32_t a0, uint32_t a1, uint32_t b0)
{
    asm volatile(
        "mma.sync.aligned.m16n8k8.row.col.f32.f16.f16.f32 "
        "{%0,%1,%2,%3}, {%4,%5}, {%6}, {%0,%1,%2,%3};"
        : "+f"(c[0]), "+f"(c[1]), "+f"(c[2]), "+f"(c[3])
        : "r"(a0), "r"(a1), "r"(b0));
}

static __device__ __forceinline__ uint32_t shfl_u32(uint32_t v, int src) {
    return __shfl_sync(0xFFFFFFFFu, v, src);
}

__global__ __launch_bounds__(TPB, 4) void router_kernel(
    const float* __restrict__ x,
    const float* __restrict__ ln_w,
    const float* __restrict__ ln_b,
    const float* __restrict__ W1,
    const float* __restrict__ b1,
    const float* __restrict__ W2,
    const float* __restrict__ b2,
    const float* __restrict__ W3,
    const float* __restrict__ b3,
    float* __restrict__ out,
    int n_rows)
{
    __shared__ float sLnW[NUM_LAYERS * 4];
    __shared__ float sLnB[NUM_LAYERS * 4];
    // W2 fragments (single fp16), both k-halves paired for LDS.64:
    // [nt*4+kt(16)][lane(32)] -> uint2 {b0 (k+0..7), b1 (k+8..15)}
    __shared__ uint2 sW2p[16 * 32];

    const int tid  = threadIdx.x;
    const int lane = tid & 31;
    const int warp = tid >> 5;
    const int g = lane >> 2;     // 0..7
    const int t = lane & 3;      // 0..3

    if (tid < NUM_LAYERS * 4) { sLnW[tid] = ln_w[tid]; sLnB[tid] = ln_b[tid]; }

    // ---- build W2 fragment table in shared (identical across warps) ----
    for (int i = tid; i < 16 * 32; i += TPB) {
        const int l    = i & 31;
        const int ntkt = i >> 5;
        const int gg = l >> 2, tt = l & 3;
        const int nt = ntkt >> 2, kt = ntkt & 3;
        const float* wrow = W2 + (8 * nt + gg) * 64 + 16 * kt + 2 * tt;
        sW2p[i] = make_uint2(h2_of(wrow[0], wrow[1]), h2_of(wrow[8], wrow[9]));
    }
    __syncthreads();

    // ---- W1 B-fragments (m16n8k8, 8 n-tiles) with b1 folded into k=5 ----
    // k = 2t, 2t+1 ; t==2 -> {W1[col][4], b1[col]} ; t==3 -> zeros
    uint32_t w1h[8];
    #pragma unroll
    for (int nt = 0; nt < 8; nt++) {
        const int col = 8 * nt + g;
        const float* wr = W1 + col * 5;
        float w0, w1v;
        if (t < 2)      { w0 = wr[2 * t]; w1v = wr[2 * t + 1]; }
        else if (t == 2){ w0 = wr[4];     w1v = b1[col]; }
        else            { w0 = 0.0f;      w1v = 0.0f; }
        w1h[nt] = h2_of(w0, w1v);
    }

    // per-lane bias/weight pairs for this lane's columns
    float2 b2v[4], w3v[4];
    #pragma unroll
    for (int nt = 0; nt < 4; nt++) {
        b2v[nt] = *reinterpret_cast<const float2*>(b2 + 8 * nt + 2 * t);
        w3v[nt] = *reinterpret_cast<const float2*>(W3 + 8 * nt + 2 * t);
    }
    const float b3v = b3[0];

    const long long warp_row0 = (long long)blockIdx.x * ROWS_PER_CTA
                              + (long long)warp * (CHUNKS_PER_WARP * 32);
    const float* xbase = x + (warp_row0 + lane) * 5;

    // preload chunk 0's row
    float cx0 = xbase[0], cx1 = xbase[1], cx2 = xbase[2], cx3 = xbase[3], cx4 = xbase[4];

    for (int ch = 0; ch < CHUNKS_PER_WARP; ch++) {
        const long long row0 = warp_row0 + ch * 32;

        // ---- prefetch next chunk's row (last chunk: harmless reload of current) ----
        const float* xn = xbase + ((ch + 1 < CHUNKS_PER_WARP) ? (ch + 1) : ch) * (32 * 5);
        const float nx0 = xn[0], nx1 = xn[1], nx2 = xn[2], nx3 = xn[3], nx4 = xn[4];

        // ---- scalar LN for row = row0 + lane ----
        const float f0 = cx0, f1 = cx1, f2 = cx2, f3 = cx3, pos = cx4;

        const float mean = (f0 + f1 + f2 + f3) * 0.25f;
        const float d0 = f0 - mean, d1 = f1 - mean, d2 = f2 - mean, d3 = f3 - mean;
        const float var  = (d0 * d0 + d1 * d1 + d2 * d2 + d3 * d3) * 0.25f;
        const float rstd = rsqrtf(var + LN_EPS);

        int lid = (int)(pos * (float)NUM_LAYERS);
        lid = max(0, min(NUM_LAYERS - 1, lid));

        const float n0 = d0 * rstd * sLnW[lid * 4 + 0] + sLnB[lid * 4 + 0];
        const float n1 = d1 * rstd * sLnW[lid * 4 + 1] + sLnB[lid * 4 + 1];
        const float n2 = d2 * rstd * sLnW[lid * 4 + 2] + sLnB[lid * 4 + 2];
        const float n3 = d3 * rstd * sLnW[lid * 4 + 3] + sLnB[lid * 4 + 3];

        // feature pairs: {n0,n1},{n2,n3},{pos,1.0} (1.0 = bias column k=5)
        uint32_t ph[3];
        ph[0] = h2_of(n0, n1);
        ph[1] = h2_of(n2, n3);
        ph[2] = h2_of(pos, 1.0f);

        #pragma unroll
        for (int mt = 0; mt < 2; mt++) {
            const int src0 = 16 * mt + g;       // row for a0
            const int src1 = src0 + 8;          // row for a1

            // transpose features via shuffle (6 shfl), then per-lane k-select
            const uint32_t s0 = shfl_u32(ph[0], src0);
            const uint32_t s1 = shfl_u32(ph[1], src0);
            const uint32_t s2 = shfl_u32(ph[2], src0);
            const uint32_t u0 = shfl_u32(ph[0], src1);
            const uint32_t u1 = shfl_u32(ph[1], src1);
            const uint32_t u2 = shfl_u32(ph[2], src1);

            const uint32_t a0 = (t == 0) ? s0 : (t == 1) ? s1 : (t == 2) ? s2 : 0u;
            const uint32_t a1 = (t == 0) ? u0 : (t == 1) ? u1 : (t == 2) ? u2 : 0u;

            // ---- layer1 per n-tile (bias via k=5), pack + half2 relu ----
            uint32_t A0[4], A1[4], A2[4], A3[4];
            #pragma unroll
            for (int nt = 0; nt < 8; nt++) {
                float c1[4] = {0.f, 0.f, 0.f, 0.f};
                mma_k8(c1, a0, a1, w1h[nt]);

                const uint32_t p01 = hmax2_zero(h2_of(c1[0], c1[1]));
                const uint32_t p23 = hmax2_zero(h2_of(c1[2], c1[3]));

                const int kt = nt >> 1;
                if ((nt & 1) == 0) {
                    A0[kt] = p01;   // (row g,   k 16kt+2t,2t+1)
                    A1[kt] = p23;   // (row g+8, k 16kt+2t,2t+1)
                } else {
                    A2[kt] = p01;   // (row g,   k 16kt+8+2t)
                    A3[kt] = p23;   // (row g+8, k 16kt+8+2t)
                }
            }

            // ---- layer2: 4 n-tiles x 4 k-tiles, W2 frags via LDS.64 ----
            float C2[4][4];
            #pragma unroll
            for (int nt = 0; nt < 4; nt++) {
                C2[nt][0] = 0.f; C2[nt][1] = 0.f; C2[nt][2] = 0.f; C2[nt][3] = 0.f;
            }
            #pragma unroll
            for (int kt = 0; kt < 4; kt++) {
                #pragma unroll
                for (int nt = 0; nt < 4; nt++) {
                    const uint2 w = sW2p[(nt * 4 + kt) * 32 + lane];
                    mma_k16(C2[nt], A0[kt], A1[kt], A2[kt], A3[kt], w.x, w.y);
                }
            }

            // ---- epilogue: +b2, relu, dot W3 over this lane's 8 cols; quad-reduce ----
            float pA = 0.f, pB = 0.f;
            #pragma unroll
            for (int nt = 0; nt < 4; nt++) {
                const float v0 = fmaxf(C2[nt][0] + b2v[nt].x, 0.0f);
                const float v1 = fmaxf(C2[nt][1] + b2v[nt].y, 0.0f);
                const float v2 = fmaxf(C2[nt][2] + b2v[nt].x, 0.0f);
                const float v3 = fmaxf(C2[nt][3] + b2v[nt].y, 0.0f);
                pA = fmaf(v0, w3v[nt].x, fmaf(v1, w3v[nt].y, pA));
                pB = fmaf(v2, w3v[nt].x, fmaf(v3, w3v[nt].y, pB));
            }
            pA += __shfl_xor_sync(0xFFFFFFFFu, pA, 1);
            pA += __shfl_xor_sync(0xFFFFFFFFu, pA, 2);
            pB += __shfl_xor_sync(0xFFFFFFFFu, pB, 1);
            pB += __shfl_xor_sync(0xFFFFFFFFu, pB, 2);
            if (t == 0) {
                out[row0 + 16 * mt + g]     = pA + b3v;
                out[row0 + 16 * mt + g + 8] = pB + b3v;
            }
        }

        // rotate prefetched row into current
        cx0 = nx0; cx1 = nx1; cx2 = nx2; cx3 = nx3; cx4 = nx4;
    }
}

extern "C" void kernel_launch(void* const* d_in, const int* in_sizes, int n_in,
                              void* d_out, int out_size)
{
    const float* x    = (const float*)d_in[0];
    const float* ln_w = (const float*)d_in[1];
    const float* ln_b = (const float*)d_in[2];
    const float* W1   = (const float*)d_in[3];
    const float* b1   = (const float*)d_in[4];
    const float* W2   = (const float*)d_in[5];
    const float* b2   = (const float*)d_in[6];
    const float* W3   = (const float*)d_in[7];
    const float* b3   = (const float*)d_in[8];
    float* out = (float*)d_out;

    const int n_rows = out_size;                    // 2,097,152
    const int blocks = n_rows / ROWS_PER_CTA;       // 2048, exact

    router_kernel<<<blocks, TPB>>>(x, ln_w, ln_b, W1, b1, W2, b2, W3, b3,
                                   out, n_rows);
}

// round 13
// speedup vs baseline: 7.7647x; 1.0006x over previous
#include <cuda_runtime.h>
#include <cuda_fp16.h>
#include <cstdint>

#define NUM_LAYERS 24
#define LN_EPS 1e-5f
#define TPB 128
#define WARPS 4
#define CHUNKS_PER_WARP 4
#define ROWS_PER_CTA (WARPS * CHUNKS_PER_WARP * 32)   // 512

// pack {a -> low 16, b -> high 16} as f16x2
static __device__ __forceinline__ uint32_t h2_of(float a, float b) {
    __half2 h = __floats2half2_rn(a, b);
    return *reinterpret_cast<uint32_t*>(&h);
}

static __device__ __forceinline__ uint32_t hmax2_zero(uint32_t v) {
    __half2 h = *reinterpret_cast<__half2*>(&v);
    __half2 z = __half2half2(__ushort_as_half(0));
    __half2 r = __hmax2(h, z);
    return *reinterpret_cast<uint32_t*>(&r);
}

static __device__ __forceinline__ uint32_t hadd2_u(uint32_t a, uint32_t b) {
    __half2 r = __hadd2(*reinterpret_cast<__half2*>(&a), *reinterpret_cast<__half2*>(&b));
    return *reinterpret_cast<uint32_t*>(&r);
}

// f16-out, f16-accum layer-1 MMA with shared zero C regs: D = A@B + 0
static __device__ __forceinline__ void mma_k8_h(
    uint32_t& d0, uint32_t& d1, uint32_t a0, uint32_t a1, uint32_t b0,
    uint32_t z0, uint32_t z1)
{
    asm volatile(
        "mma.sync.aligned.m16n8k8.row.col.f16.f16.f16.f16 "
        "{%0,%1}, {%2,%3}, {%4}, {%5,%6};"
        : "=r"(d0), "=r"(d1)
        : "r"(a0), "r"(a1), "r"(b0), "r"(z0), "r"(z1));
}

// f32 k16 MMA, in-place accumulate
static __device__ __forceinline__ void mma_k16(
    float* c, uint32_t a0, uint32_t a1, uint32_t a2, uint32_t a3,
    uint32_t b0, uint32_t b1)
{
    asm volatile(
        "mma.sync.aligned.m16n8k16.row.col.f32.f16.f16.f32 "
        "{%0,%1,%2,%3}, {%4,%5,%6,%7}, {%8,%9}, {%0,%1,%2,%3};"
        : "+f"(c[0]), "+f"(c[1]), "+f"(c[2]), "+f"(c[3])
        : "r"(a0), "r"(a1), "r"(a2), "r"(a3), "r"(b0), "r"(b1));
}

// f32 k16 MMA, D = A@B + {zf,zf,zf,zf} (fresh accumulators, no MOV-zero chain)
static __device__ __forceinline__ void mma_k16_z(
    float* c, uint32_t a0, uint32_t a1, uint32_t a2, uint32_t a3,
    uint32_t b0, uint32_t b1, float zf)
{
    asm volatile(
        "mma.sync.aligned.m16n8k16.row.col.f32.f16.f16.f32 "
        "{%0,%1,%2,%3}, {%4,%5,%6,%7}, {%8,%9}, {%10,%11,%12,%13};"
        : "=f"(c[0]), "=f"(c[1]), "=f"(c[2]), "=f"(c[3])
        : "r"(a0), "r"(a1), "r"(a2), "r"(a3), "r"(b0), "r"(b1),
          "f"(zf), "f"(zf), "f"(zf), "f"(zf));
}

static __device__ __forceinline__ uint32_t shfl_u32(uint32_t v, int src) {
    return __shfl_sync(0xFFFFFFFFu, v, src);
}

__global__ __launch_bounds__(TPB, 4) void router_kernel(
    const float* __restrict__ x,
    const float* __restrict__ ln_w,
    const float* __restrict__ ln_b,
    const float* __restrict__ W1,
    const float* __restrict__ b1,
    const float* __restrict__ W2,
    const float* __restrict__ b2,
    const float* __restrict__ W3,
    const float* __restrict__ b3,
    float* __restrict__ out,
    int n_rows)
{
    __shared__ float sLnW[NUM_LAYERS * 4];
    __shared__ float sLnB[NUM_LAYERS * 4];
    // W2 fragments (fp16), k-halves paired for LDS.64: [nt*4+kt][lane] -> {b0, b1}
    __shared__ uint2 sW2p[16 * 32];

    const int tid  = threadIdx.x;
    const int lane = tid & 31;
    const int warp = tid >> 5;
    const int g = lane >> 2;     // 0..7
    const int t = lane & 3;      // 0..3

    if (tid < NUM_LAYERS * 4) { sLnW[tid] = ln_w[tid]; sLnB[tid] = ln_b[tid]; }

    // ---- build W2 fragment table in shared ----
    for (int i = tid; i < 16 * 32; i += TPB) {
        const int l    = i & 31;
        const int ntkt = i >> 5;
        const int gg = l >> 2, tt = l & 3;
        const int nt = ntkt >> 2, kt = ntkt & 3;
        const float* wrow = W2 + (8 * nt + gg) * 64 + 16 * kt + 2 * tt;
        sW2p[i] = make_uint2(h2_of(wrow[0], wrow[1]), h2_of(wrow[8], wrow[9]));
    }
    __syncthreads();

    // ---- W1 B-fragments (m16n8k8) with b1 folded into k=5; t==3 -> zeros ----
    uint32_t w1h[8];
    #pragma unroll
    for (int nt = 0; nt < 8; nt++) {
        const int col = 8 * nt + g;
        const float* wr = W1 + col * 5;
        float w0, w1v;
        if (t < 2)      { w0 = wr[2 * t]; w1v = wr[2 * t + 1]; }
        else if (t == 2){ w0 = wr[4];     w1v = b1[col]; }
        else            { w0 = 0.0f;      w1v = 0.0f; }
        w1h[nt] = h2_of(w0, w1v);
    }

    // b2 packed pairs for this lane's columns (cols 8nt+2t, +1)
    uint32_t b2p[4];
    #pragma unroll
    for (int nt = 0; nt < 4; nt++)
        b2p[nt] = h2_of(b2[8 * nt + 2 * t], b2[8 * nt + 2 * t + 1]);

    // W3 B-fragments for the epilogue MMA (n=0 column lives in g==0 lanes)
    uint32_t w3f[4];   // [kt'*2 + half]
    #pragma unroll
    for (int ktp = 0; ktp < 2; ktp++) {
        if (g == 0) {
            w3f[ktp * 2 + 0] = h2_of(W3[16 * ktp + 2 * t],     W3[16 * ktp + 2 * t + 1]);
            w3f[ktp * 2 + 1] = h2_of(W3[16 * ktp + 8 + 2 * t], W3[16 * ktp + 8 + 2 * t + 1]);
        } else {
            w3f[ktp * 2 + 0] = 0u;
            w3f[ktp * 2 + 1] = 0u;
        }
    }
    const float b3v = b3[0];

    const uint32_t zU = 0u;
    const float zF = 0.0f;

    const long long warp_row0 = (long long)blockIdx.x * ROWS_PER_CTA
                              + (long long)warp * (CHUNKS_PER_WARP * 32);
    const float* xbase = x + (warp_row0 + lane) * 5;

    // preload chunk 0's row
    float cx0 = xbase[0], cx1 = xbase[1], cx2 = xbase[2], cx3 = xbase[3], cx4 = xbase[4];

    for (int ch = 0; ch < CHUNKS_PER_WARP; ch++) {
        const long long row0 = warp_row0 + ch * 32;

        // ---- prefetch next chunk's row ----
        const float* xn = xbase + ((ch + 1 < CHUNKS_PER_WARP) ? (ch + 1) : ch) * (32 * 5);
        const float nx0 = xn[0], nx1 = xn[1], nx2 = xn[2], nx3 = xn[3], nx4 = xn[4];

        // ---- scalar LN for row = row0 + lane ----
        const float f0 = cx0, f1 = cx1, f2 = cx2, f3 = cx3, pos = cx4;

        const float mean = (f0 + f1 + f2 + f3) * 0.25f;
        const float d0 = f0 - mean, d1 = f1 - mean, d2 = f2 - mean, d3 = f3 - mean;
        const float var  = (d0 * d0 + d1 * d1 + d2 * d2 + d3 * d3) * 0.25f;
        const float rstd = rsqrtf(var + LN_EPS);

        int lid = (int)(pos * (float)NUM_LAYERS);
        lid = max(0, min(NUM_LAYERS - 1, lid));

        const float n0 = d0 * rstd * sLnW[lid * 4 + 0] + sLnB[lid * 4 + 0];
        const float n1 = d1 * rstd * sLnW[lid * 4 + 1] + sLnB[lid * 4 + 1];
        const float n2 = d2 * rstd * sLnW[lid * 4 + 2] + sLnB[lid * 4 + 2];
        const float n3 = d3 * rstd * sLnW[lid * 4 + 3] + sLnB[lid * 4 + 3];

        // feature pairs: {n0,n1},{n2,n3},{pos,1.0} (1.0 = bias column k=5)
        uint32_t ph[3];
        ph[0] = h2_of(n0, n1);
        ph[1] = h2_of(n2, n3);
        ph[2] = h2_of(pos, 1.0f);

        #pragma unroll
        for (int mt = 0; mt < 2; mt++) {
            const int src0 = 16 * mt + g;
            const int src1 = src0 + 8;

            const uint32_t s0 = shfl_u32(ph[0], src0);
            const uint32_t s1 = shfl_u32(ph[1], src0);
            const uint32_t s2 = shfl_u32(ph[2], src0);
            const uint32_t u0 = shfl_u32(ph[0], src1);
            const uint32_t u1 = shfl_u32(ph[1], src1);
            const uint32_t u2 = shfl_u32(ph[2], src1);

            const uint32_t a0 = (t == 0) ? s0 : (t == 1) ? s1 : (t == 2) ? s2 : 0u;
            const uint32_t a1 = (t == 0) ? u0 : (t == 1) ? u1 : (t == 2) ? u2 : 0u;

            // ---- layer1: f16-out MMA, D already in layer2 A-frag pair layout ----
            uint32_t A0[4], A1[4], A2[4], A3[4];
            #pragma unroll
            for (int nt = 0; nt < 8; nt++) {
                uint32_t p01, p23;
                mma_k8_h(p01, p23, a0, a1, w1h[nt], zU, zU);
                p01 = hmax2_zero(p01);
                p23 = hmax2_zero(p23);
                const int kt = nt >> 1;
                if ((nt & 1) == 0) { A0[kt] = p01; A1[kt] = p23; }
                else               { A2[kt] = p01; A3[kt] = p23; }
            }

            // ---- layer2: kt=0 with fresh accumulators, kt=1..3 in-place ----
            float C2[4][4];
            #pragma unroll
            for (int nt = 0; nt < 4; nt++) {
                const uint2 w = sW2p[(nt * 4) * 32 + lane];
                mma_k16_z(C2[nt], A0[0], A1[0], A2[0], A3[0], w.x, w.y, zF);
            }
            #pragma unroll
            for (int kt = 1; kt < 4; kt++) {
                #pragma unroll
                for (int nt = 0; nt < 4; nt++) {
                    const uint2 w = sW2p[(nt * 4 + kt) * 32 + lane];
                    mma_k16(C2[nt], A0[kt], A1[kt], A2[kt], A3[kt], w.x, w.y);
                }
            }

            // ---- epilogue: pack + b2 + relu in half2, W3 dot via chained MMA ----
            uint32_t e0[4], e1[4];
            #pragma unroll
            for (int nt = 0; nt < 4; nt++) {
                e0[nt] = hmax2_zero(hadd2_u(h2_of(C2[nt][0], C2[nt][1]), b2p[nt]));
                e1[nt] = hmax2_zero(hadd2_u(h2_of(C2[nt][2], C2[nt][3]), b2p[nt]));
            }
            float S[4];
            mma_k16_z(S, e0[0], e1[0], e0[1], e1[1], w3f[0], w3f[1], zF);
            mma_k16 (S, e0[2], e1[2], e0[3], e1[3], w3f[2], w3f[3]);

            if (t == 0) {
                out[row0 + 16 * mt + g]     = S[0] + b3v;   // D[g][0]
                out[row0 + 16 * mt + g + 8] = S[2] + b3v;   // D[g+8][0]
            }
        }

        cx0 = nx0; cx1 = nx1; cx2 = nx2; cx3 = nx3; cx4 = nx4;
    }
}

extern "C" void kernel_launch(void* const* d_in, const int* in_sizes, int n_in,
                              void* d_out, int out_size)
{
    const float* x    = (const float*)d_in[0];
    const float* ln_w = (const float*)d_in[1];
    const float* ln_b = (const float*)d_in[2];
    const float* W1   = (const float*)d_in[3];
    const float* b1   = (const float*)d_in[4];
    const float* W2   = (const float*)d_in[5];
    const float* b2   = (const float*)d_in[6];
    const float* W3   = (const float*)d_in[7];
    const float* b3   = (const float*)d_in[8];
    float* out = (float*)d_out;

    const int n_rows = out_size;                    // 2,097,152
    const int blocks = n_rows / ROWS_PER_CTA;       // 4096, exact

    router_kernel<<<blocks, TPB>>>(x, ln_w, ln_b, W1, b1, W2, b2, W3, b3,
                                   out, n_rows);
}